// round 1
// baseline (speedup 1.0000x reference)
#include <cuda_runtime.h>
#include <math.h>

#define NE      8
#define HIDDEN  2048
#define INTER   768
#define O2      (2*INTER)     // 1536
#define NROT    4
#define TOKENS  4096
#define NASSIGN (TOKENS*2)    // 8192
#define CAP     NASSIGN
#define QMAXF   15.0f

// ---------------- scratch (device globals; no allocation allowed) ----------------
__device__ float g_gup[NE*O2*HIDDEN];        // quantized gate_up weights
__device__ float g_dwn[NE*HIDDEN*INTER];     // quantized down weights
__device__ float g_hbuf[NASSIGN*O2];         // gate/up pre-activation per assignment
__device__ float g_inter[NASSIGN*INTER];     // silu(gate)*up
__device__ float g_ybuf[NASSIGN*HIDDEN];     // down output per assignment
__device__ int   g_cnt[NE];
__device__ int   g_perm[NE*CAP];
__device__ int   g_tiles[192];
__device__ int   g_ntiles;
__device__ float g_cgu[NROT*HIDDEN/2], g_sgu[NROT*HIDDEN/2];
__device__ float g_cdn[NROT*INTER/2],  g_sdn[NROT*INTER/2];

// ---------------- trig tables in double (immune to --use_fast_math) ----------------
__global__ void k_trig(const float* __restrict__ ga, const float* __restrict__ da) {
    int i = blockIdx.x*blockDim.x + threadIdx.x;
    if (i < NROT*HIDDEN/2) {
        double a = (double)ga[i];
        g_cgu[i] = (float)cos(a);
        g_sgu[i] = (float)sin(a);
    }
    if (i < NROT*INTER/2) {
        double a = (double)da[i];
        g_cdn[i] = (float)cos(a);
        g_sdn[i] = (float)sin(a);
    }
}

// ---------------- per-row pseudo-quantization ----------------
// One CTA per weight row. Row lives in SMEM. IN = 2048 (gate_up) or 768 (down).
template<int IN, bool GU>
__global__ __launch_bounds__(256) void k_prep(const float* __restrict__ W,
                                              const int*   __restrict__ pairs,
                                              const float* __restrict__ ch) {
    __shared__ float w[IN];
    constexpr int NG = IN/128;
    __shared__ float gscale[NG], gzero[NG];

    const int row = blockIdx.x;
    const int tid = threadIdx.x;
    const int NT  = 256;
    const float* src = W + (size_t)row*IN;
    const float* ctab = GU ? g_cgu : g_cdn;
    const float* stab = GU ? g_sgu : g_sdn;
    float* out = (GU ? g_gup : g_dwn) + (size_t)row*IN;

    for (int i = tid; i < IN; i += NT) w[i] = __fmul_rn(src[i], ch[i]);
    __syncthreads();

    // forward rotations
    for (int r = 0; r < NROT; r++) {
        const int*   pr = pairs + r*IN;
        const float* cr = ctab + r*(IN/2);
        const float* sr = stab + r*(IN/2);
        for (int p = tid; p < IN/2; p += NT) {
            int base = (2*p) & ~127;
            int ii = base + pr[2*p];
            int jj = base + pr[2*p+1];
            float c = cr[p], s = sr[p];
            float wi = w[ii], wj = w[jj];
            w[ii] = __fsub_rn(__fmul_rn(c, wi), __fmul_rn(s, wj));
            w[jj] = __fadd_rn(__fmul_rn(s, wi), __fmul_rn(c, wj));
        }
        __syncthreads();
    }

    // fake quant per 128-group: one warp per group
    {
        int warp = tid >> 5, lane = tid & 31;
        for (int g = warp; g < NG; g += NT/32) {
            float mx = -INFINITY, mn = INFINITY;
            for (int k = lane; k < 128; k += 32) {
                float v = w[g*128 + k];
                mx = fmaxf(mx, v); mn = fminf(mn, v);
            }
            for (int o = 16; o; o >>= 1) {
                mx = fmaxf(mx, __shfl_xor_sync(0xffffffffu, mx, o));
                mn = fminf(mn, __shfl_xor_sync(0xffffffffu, mn, o));
            }
            if (lane == 0) {
                float d  = fmaxf(__fsub_rn(mx, mn), 1e-5f);
                float sc = __fdiv_rn(d, QMAXF);
                gscale[g] = sc;
                gzero[g]  = rintf(__fdiv_rn(__fmul_rn(mn, -1.0f), sc));
            }
        }
    }
    __syncthreads();
    for (int i = tid; i < IN; i += NT) {
        int g = i >> 7;
        float sc = gscale[g], z = gzero[g];
        float q = __fadd_rn(rintf(__fdiv_rn(w[i], sc)), z);
        q = fminf(fmaxf(q, 0.0f), QMAXF);
        w[i] = __fmul_rn(__fsub_rn(q, z), sc);
    }
    __syncthreads();

    // inverse rotations (pairs reversed, angles negated: c same, s -> -s)
    for (int r = NROT-1; r >= 0; r--) {
        const int*   pr = pairs + r*IN;
        const float* cr = ctab + r*(IN/2);
        const float* sr = stab + r*(IN/2);
        for (int p = tid; p < IN/2; p += NT) {
            int base = (2*p) & ~127;
            int ii = base + pr[2*p];
            int jj = base + pr[2*p+1];
            float c = cr[p], s = sr[p];
            float wi = w[ii], wj = w[jj];
            w[ii] = __fadd_rn(__fmul_rn(c, wi), __fmul_rn(s, wj));
            w[jj] = __fsub_rn(__fmul_rn(c, wj), __fmul_rn(s, wi));
        }
        __syncthreads();
    }

    for (int i = tid; i < IN; i += NT) out[i] = __fdiv_rn(w[i], ch[i]);
}

// ---------------- routing ----------------
__global__ void k_zero() { if (threadIdx.x < NE) g_cnt[threadIdx.x] = 0; }

__global__ void k_route(const int* __restrict__ idx) {
    int a = blockIdx.x*blockDim.x + threadIdx.x;
    if (a < NASSIGN) {
        int e = idx[a];
        int slot = atomicAdd(&g_cnt[e], 1);
        g_perm[e*CAP + slot] = a;
    }
}

__global__ void k_tiles() {
    if (threadIdx.x == 0) {
        int nt = 0;
        for (int e = 0; e < NE; e++) {
            int c = g_cnt[e];
            for (int m0 = 0; m0 < c; m0 += 64) g_tiles[nt++] = (e << 20) | m0;
        }
        g_ntiles = nt;
    }
}

// ---------------- grouped NT GEMM: C[a][n] = sum_k A[a][k] * B[e][n][k] ----------
// MODE 0: A = hidden (row = assignment>>1), B = g_gup, C = g_hbuf   (KD=2048, ND=1536)
// MODE 1: A = g_inter (row = assignment),   B = g_dwn, C = g_ybuf   (KD=768,  ND=2048)
template<int KD, int ND, int MODE>
__global__ __launch_bounds__(256) void k_gemm(const float* __restrict__ Aext) {
    int tileIdx = blockIdx.y;
    if (tileIdx >= g_ntiles) return;
    int packed = g_tiles[tileIdx];
    int e  = packed >> 20;
    int m0 = packed & 0xFFFFF;
    int n0 = blockIdx.x * 64;

    const float* Abase = (MODE == 0) ? Aext : g_inter;
    const int    lda   = (MODE == 0) ? HIDDEN : INTER;
    const float* B     = ((MODE == 0) ? g_gup : g_dwn) + (size_t)e*ND*KD;
    float*       Cbase = (MODE == 0) ? g_hbuf : g_ybuf;
    const int    ldc   = (MODE == 0) ? O2 : HIDDEN;

    __shared__ __align__(16) float As[16][68];
    __shared__ __align__(16) float Bs[16][68];
    __shared__ int arow[64];

    const int tid = threadIdx.x;
    const int tx = tid & 15, ty = tid >> 4;

    if (tid < 64) {
        int m = m0 + tid;
        arow[tid] = (m < g_cnt[e]) ? g_perm[e*CAP + m] : -1;
    }
    __syncthreads();

    const int lrow = tid >> 2;         // 0..63
    const int lk4  = (tid & 3) * 4;    // 0,4,8,12
    int aasn = arow[lrow];
    const float* Arow = (aasn >= 0)
        ? Abase + (size_t)((MODE == 0) ? (aasn >> 1) : aasn) * lda
        : nullptr;
    const float* Brow = B + (size_t)(n0 + lrow) * KD;

    float acc[4][4] = {};

    for (int k0 = 0; k0 < KD; k0 += 16) {
        float4 av = Arow ? *(const float4*)(Arow + k0 + lk4) : make_float4(0,0,0,0);
        float4 bv = *(const float4*)(Brow + k0 + lk4);
        As[lk4+0][lrow] = av.x; As[lk4+1][lrow] = av.y;
        As[lk4+2][lrow] = av.z; As[lk4+3][lrow] = av.w;
        Bs[lk4+0][lrow] = bv.x; Bs[lk4+1][lrow] = bv.y;
        Bs[lk4+2][lrow] = bv.z; Bs[lk4+3][lrow] = bv.w;
        __syncthreads();
        #pragma unroll
        for (int k = 0; k < 16; k++) {
            float4 ra = *(const float4*)&As[k][ty*4];
            float4 rb = *(const float4*)&Bs[k][tx*4];
            acc[0][0] += ra.x*rb.x; acc[0][1] += ra.x*rb.y; acc[0][2] += ra.x*rb.z; acc[0][3] += ra.x*rb.w;
            acc[1][0] += ra.y*rb.x; acc[1][1] += ra.y*rb.y; acc[1][2] += ra.y*rb.z; acc[1][3] += ra.y*rb.w;
            acc[2][0] += ra.z*rb.x; acc[2][1] += ra.z*rb.y; acc[2][2] += ra.z*rb.z; acc[2][3] += ra.z*rb.w;
            acc[3][0] += ra.w*rb.x; acc[3][1] += ra.w*rb.y; acc[3][2] += ra.w*rb.z; acc[3][3] += ra.w*rb.w;
        }
        __syncthreads();
    }

    #pragma unroll
    for (int i = 0; i < 4; i++) {
        int a = arow[ty*4 + i];
        if (a >= 0) {
            float* Crow = Cbase + (size_t)a*ldc + n0 + tx*4;
            Crow[0] = acc[i][0]; Crow[1] = acc[i][1];
            Crow[2] = acc[i][2]; Crow[3] = acc[i][3];
        }
    }
}

// ---------------- activation ----------------
__global__ void k_silu() {
    int i = blockIdx.x*blockDim.x + threadIdx.x;
    if (i < NASSIGN*INTER) {
        int a = i / INTER;
        int c = i - a*INTER;
        float g = g_hbuf[(size_t)a*O2 + c];
        float u = g_hbuf[(size_t)a*O2 + INTER + c];
        float sg = g / (1.0f + expf(-g));
        g_inter[i] = sg * u;
    }
}

// ---------------- combine ----------------
__global__ void k_comb(const float* __restrict__ wts, float* __restrict__ out) {
    int i = blockIdx.x*blockDim.x + threadIdx.x;
    if (i < TOKENS*HIDDEN) {
        int t = i >> 11;        // /HIDDEN
        int h = i & (HIDDEN-1);
        float r = wts[2*t]   * g_ybuf[(size_t)(2*t)  *HIDDEN + h]
                + wts[2*t+1] * g_ybuf[(size_t)(2*t+1)*HIDDEN + h];
        out[i] = r;
    }
}

// ---------------- launch ----------------
extern "C" void kernel_launch(void* const* d_in, const int* in_sizes, int n_in,
                              void* d_out, int out_size) {
    const float* hidden  = (const float*)d_in[0];
    const int*   topk    = (const int*)  d_in[1];
    const float* topw    = (const float*)d_in[2];
    const float* gup_w   = (const float*)d_in[3];
    const float* dwn_w   = (const float*)d_in[4];
    const int*   gup_p   = (const int*)  d_in[5];
    const float* gup_a   = (const float*)d_in[6];
    const int*   dwn_p   = (const int*)  d_in[7];
    const float* dwn_a   = (const float*)d_in[8];
    const float* gup_ch  = (const float*)d_in[9];
    const float* dwn_ch  = (const float*)d_in[10];
    float* out = (float*)d_out;

    k_trig<<<(NROT*HIDDEN/2 + 255)/256, 256>>>(gup_a, dwn_a);
    k_prep<HIDDEN, true ><<<NE*O2,     256>>>(gup_w, gup_p, gup_ch);
    k_prep<INTER,  false><<<NE*HIDDEN, 256>>>(dwn_w, dwn_p, dwn_ch);
    k_zero<<<1, 32>>>();
    k_route<<<(NASSIGN + 255)/256, 256>>>(topk);
    k_tiles<<<1, 32>>>();
    k_gemm<HIDDEN, O2,     0><<<dim3(O2/64,     136), 256>>>(hidden);
    k_silu<<<(NASSIGN*INTER + 255)/256, 256>>>();
    k_gemm<INTER,  HIDDEN, 1><<<dim3(HIDDEN/64, 136), 256>>>(nullptr);
    k_comb<<<(TOKENS*HIDDEN + 255)/256, 256>>>(topw, out);
}

// round 4
// speedup vs baseline: 3.3307x; 3.3307x over previous
#include <cuda_runtime.h>
#include <cuda_fp16.h>
#include <math.h>
#include <stdint.h>

#define NE      8
#define HIDDEN  2048
#define INTER   768
#define O2      (2*INTER)     // 1536
#define NROT    4
#define TOKENS  4096
#define NASSIGN (TOKENS*2)    // 8192
#define CAP     NASSIGN
#define QMAXF   15.0f

// ---------------- scratch (device globals; no allocation allowed) ----------------
__device__ __half g_gup[NE*O2*HIDDEN];       // quantized gate_up weights (fp16)
__device__ __half g_dwn[NE*HIDDEN*INTER];    // quantized down weights (fp16)
__device__ __half g_h[TOKENS*HIDDEN];        // hidden states (fp16)
__device__ __half g_i[NASSIGN*INTER];        // silu(gate)*up (fp16)
__device__ float  g_hbuf[NASSIGN*O2];        // gate/up pre-activation (fp32)
__device__ float  g_ybuf[NASSIGN*HIDDEN];    // down output (fp32)
__device__ int    g_cnt[NE];
__device__ int    g_perm[NE*CAP];
__device__ int    g_tiles[128];
__device__ int    g_ntiles;
__device__ float  g_cgu[NROT*HIDDEN/2], g_sgu[NROT*HIDDEN/2];
__device__ float  g_cdn[NROT*INTER/2],  g_sdn[NROT*INTER/2];

__device__ __forceinline__ uint32_t smem_u32(const void* p) {
    uint32_t a;
    asm("{ .reg .u64 t; cvta.to.shared.u64 t, %1; cvt.u32.u64 %0, t; }" : "=r"(a) : "l"(p));
    return a;
}

// ---------------- trig tables in double (immune to --use_fast_math) ----------------
__global__ void k_trig(const float* __restrict__ ga, const float* __restrict__ da) {
    int i = blockIdx.x*blockDim.x + threadIdx.x;
    if (i < NROT*HIDDEN/2) {
        double a = (double)ga[i];
        g_cgu[i] = (float)cos(a);
        g_sgu[i] = (float)sin(a);
    }
    if (i < NROT*INTER/2) {
        double a = (double)da[i];
        g_cdn[i] = (float)cos(a);
        g_sdn[i] = (float)sin(a);
    }
}

// ---------------- per-row pseudo-quantization -> fp16 ----------------
template<int IN, bool GU>
__global__ __launch_bounds__(256) void k_prep(const float* __restrict__ W,
                                              const int*   __restrict__ pairs,
                                              const float* __restrict__ ch) {
    __shared__ float w[IN];
    constexpr int NG = IN/128;
    __shared__ float gscale[NG], gzero[NG];

    const int row = blockIdx.x;
    const int tid = threadIdx.x;
    const int NT  = 256;
    const float* src = W + (size_t)row*IN;
    const float* ctab = GU ? g_cgu : g_cdn;
    const float* stab = GU ? g_sgu : g_sdn;
    __half* out = (GU ? g_gup : g_dwn) + (size_t)row*IN;

    for (int i = tid; i < IN; i += NT) w[i] = __fmul_rn(src[i], ch[i]);
    __syncthreads();

    for (int r = 0; r < NROT; r++) {
        const int*   pr = pairs + r*IN;
        const float* cr = ctab + r*(IN/2);
        const float* sr = stab + r*(IN/2);
        for (int p = tid; p < IN/2; p += NT) {
            int base = (2*p) & ~127;
            int ii = base + pr[2*p];
            int jj = base + pr[2*p+1];
            float c = cr[p], s = sr[p];
            float wi = w[ii], wj = w[jj];
            w[ii] = __fsub_rn(__fmul_rn(c, wi), __fmul_rn(s, wj));
            w[jj] = __fadd_rn(__fmul_rn(s, wi), __fmul_rn(c, wj));
        }
        __syncthreads();
    }

    {
        int warp = tid >> 5, lane = tid & 31;
        for (int g = warp; g < NG; g += NT/32) {
            float mx = -INFINITY, mn = INFINITY;
            for (int k = lane; k < 128; k += 32) {
                float v = w[g*128 + k];
                mx = fmaxf(mx, v); mn = fminf(mn, v);
            }
            for (int o = 16; o; o >>= 1) {
                mx = fmaxf(mx, __shfl_xor_sync(0xffffffffu, mx, o));
                mn = fminf(mn, __shfl_xor_sync(0xffffffffu, mn, o));
            }
            if (lane == 0) {
                float d  = fmaxf(__fsub_rn(mx, mn), 1e-5f);
                float sc = __fdiv_rn(d, QMAXF);
                gscale[g] = sc;
                gzero[g]  = rintf(__fdiv_rn(__fmul_rn(mn, -1.0f), sc));
            }
        }
    }
    __syncthreads();
    for (int i = tid; i < IN; i += NT) {
        int g = i >> 7;
        float sc = gscale[g], z = gzero[g];
        float q = __fadd_rn(rintf(__fdiv_rn(w[i], sc)), z);
        q = fminf(fmaxf(q, 0.0f), QMAXF);
        w[i] = __fmul_rn(__fsub_rn(q, z), sc);
    }
    __syncthreads();

    for (int r = NROT-1; r >= 0; r--) {
        const int*   pr = pairs + r*IN;
        const float* cr = ctab + r*(IN/2);
        const float* sr = stab + r*(IN/2);
        for (int p = tid; p < IN/2; p += NT) {
            int base = (2*p) & ~127;
            int ii = base + pr[2*p];
            int jj = base + pr[2*p+1];
            float c = cr[p], s = sr[p];
            float wi = w[ii], wj = w[jj];
            w[ii] = __fadd_rn(__fmul_rn(c, wi), __fmul_rn(s, wj));
            w[jj] = __fsub_rn(__fmul_rn(c, wj), __fmul_rn(s, wi));
        }
        __syncthreads();
    }

    for (int i = tid; i < IN; i += NT)
        out[i] = __float2half_rn(__fdiv_rn(w[i], ch[i]));
}

// ---------------- hidden -> fp16 ----------------
__global__ void k_hsplit(const float* __restrict__ hs) {
    int i = blockIdx.x*blockDim.x + threadIdx.x;
    if (i < TOKENS*HIDDEN) g_h[i] = __float2half_rn(hs[i]);
}

// ---------------- routing ----------------
__global__ void k_zero() { if (threadIdx.x < NE) g_cnt[threadIdx.x] = 0; }

__global__ void k_route(const int* __restrict__ idx) {
    int a = blockIdx.x*blockDim.x + threadIdx.x;
    if (a < NASSIGN) {
        int e = idx[a];
        int slot = atomicAdd(&g_cnt[e], 1);
        g_perm[e*CAP + slot] = a;
    }
}

__global__ void k_tiles() {
    if (threadIdx.x == 0) {
        int nt = 0;
        for (int e = 0; e < NE; e++) {
            int c = g_cnt[e];
            for (int m0 = 0; m0 < c; m0 += 128) g_tiles[nt++] = (e << 20) | m0;
        }
        g_ntiles = nt;
    }
}

// ---------------- grouped HMMA GEMM ----------------
// C[a][n] = sum_k A[a][k] * B[e][n][k], fp16 inputs, fp32 accum.
// CTA tile M=128 x N=128, K-stage 32, double-buffered cp.async.
// 8 warps: warp_m = wid&1 (64 rows), warp_n = wid>>1 (32 cols).
// MODE 0: A = g_h (row = assignment>>1), B = g_gup, C = g_hbuf  (KD=2048)
// MODE 1: A = g_i (row = assignment),    B = g_dwn, C = g_ybuf  (KD=768)
#define PAD 40   // halves per row in smem (80B, 16B-aligned, conflict-free ldsm)

template<int KD, int MODE>
__global__ __launch_bounds__(256, 2) void k_gemm() {
    const int tileIdx = blockIdx.x;
    if (tileIdx >= g_ntiles) return;
    const int packed = g_tiles[tileIdx];
    const int e  = packed >> 20;
    const int m0 = packed & 0xFFFFF;
    const int n0 = blockIdx.y * 128;
    constexpr int NST = KD / 32;

    __shared__ __align__(16) __half As[2][128*PAD];
    __shared__ __align__(16) __half Bs[2][128*PAD];
    __shared__ int s_arow[128];

    const int tid  = threadIdx.x;
    const int wid  = tid >> 5, lane = tid & 31;

    if (tid < 128) {
        int m = m0 + tid;
        s_arow[tid] = (m < g_cnt[e]) ? g_perm[e*CAP + m] : -1;
    }
    __syncthreads();

    const __half* Ag = MODE ? g_i : g_h;
    const __half* Bg = (MODE ? g_dwn : g_gup) + (size_t)e*(MODE?HIDDEN:O2)*KD;

    // cp.async plan: per stage 512 16B-chunks for A, 512 for B; 2 each per thread
    const __half* srcA[2]; uint32_t dstA[2]; uint32_t szA[2];
    const __half* srcB[2]; uint32_t dstB[2];
    #pragma unroll
    for (int j = 0; j < 2; j++) {
        int idx = tid*2 + j;            // 0..511
        int r = idx >> 2, c16 = idx & 3;
        int a = s_arow[r];
        int arowg = MODE ? a : (a >> 1);
        srcA[j] = (a >= 0) ? Ag + (size_t)arowg*KD + c16*8 : Ag;
        szA[j]  = (a >= 0) ? 16u : 0u;
        dstA[j] = (uint32_t)((r*PAD + c16*8) * 2);
        srcB[j] = Bg + (size_t)(n0 + r)*KD + c16*8;
        dstB[j] = dstA[j];
    }
    const uint32_t aBase0 = smem_u32(&As[0][0]), aBase1 = smem_u32(&As[1][0]);
    const uint32_t bBase0 = smem_u32(&Bs[0][0]), bBase1 = smem_u32(&Bs[1][0]);

    float acc[4][4][4];
    #pragma unroll
    for (int i = 0; i < 4; i++)
        #pragma unroll
        for (int j = 0; j < 4; j++)
            #pragma unroll
            for (int q = 0; q < 4; q++) acc[i][j][q] = 0.0f;

    const int mBase = (wid & 1) * 64;
    const int nBase = (wid >> 1) * 32;
    // ldmatrix source offsets (within a stage buffer, in bytes)
    uint32_t aoff[4], boff[4];
    #pragma unroll
    for (int mi = 0; mi < 4; mi++) {
        int r = mBase + mi*16 + (lane & 15);
        int kk = (lane >> 4) * 8;
        aoff[mi] = (uint32_t)((r*PAD + kk) * 2);
    }
    #pragma unroll
    for (int ni = 0; ni < 4; ni++) {
        int r = nBase + ni*8 + (lane & 7);
        int kk = ((lane >> 3) & 1) * 8;
        boff[ni] = (uint32_t)((r*PAD + kk) * 2);
    }

    #define PREFETCH(st, buf) do {                                             \
        const int k0_ = (st) * 32;                                             \
        uint32_t ab = (buf) ? aBase1 : aBase0;                                 \
        uint32_t bb = (buf) ? bBase1 : bBase0;                                 \
        _Pragma("unroll")                                                      \
        for (int j = 0; j < 2; j++) {                                          \
            asm volatile("cp.async.ca.shared.global [%0], [%1], 16, %2;"       \
                :: "r"(ab + dstA[j]), "l"(srcA[j] + k0_), "r"(szA[j]));        \
            asm volatile("cp.async.ca.shared.global [%0], [%1], 16;"           \
                :: "r"(bb + dstB[j]), "l"(srcB[j] + k0_));                     \
        }                                                                      \
        asm volatile("cp.async.commit_group;");                                \
    } while (0)

    PREFETCH(0, 0);

    for (int s = 0; s < NST; s++) {
        if (s + 1 < NST) {
            PREFETCH(s + 1, (s + 1) & 1);
            asm volatile("cp.async.wait_group 1;");
        } else {
            asm volatile("cp.async.wait_group 0;");
        }
        __syncthreads();
        uint32_t ab = (s & 1) ? aBase1 : aBase0;
        uint32_t bb = (s & 1) ? bBase1 : bBase0;
        #pragma unroll
        for (int ks = 0; ks < 2; ks++) {
            uint32_t a[4][4], b[4][2];
            #pragma unroll
            for (int mi = 0; mi < 4; mi++)
                asm volatile("ldmatrix.sync.aligned.m8n8.x4.shared.b16 {%0,%1,%2,%3}, [%4];"
                    : "=r"(a[mi][0]), "=r"(a[mi][1]), "=r"(a[mi][2]), "=r"(a[mi][3])
                    : "r"(ab + aoff[mi] + ks*32));
            #pragma unroll
            for (int ni = 0; ni < 4; ni++)
                asm volatile("ldmatrix.sync.aligned.m8n8.x2.shared.b16 {%0,%1}, [%2];"
                    : "=r"(b[ni][0]), "=r"(b[ni][1])
                    : "r"(bb + boff[ni] + ks*32));
            #pragma unroll
            for (int mi = 0; mi < 4; mi++)
                #pragma unroll
                for (int ni = 0; ni < 4; ni++)
                    asm volatile(
                        "mma.sync.aligned.m16n8k16.row.col.f32.f16.f16.f32 "
                        "{%0,%1,%2,%3}, {%4,%5,%6,%7}, {%8,%9}, {%0,%1,%2,%3};"
                        : "+f"(acc[mi][ni][0]), "+f"(acc[mi][ni][1]),
                          "+f"(acc[mi][ni][2]), "+f"(acc[mi][ni][3])
                        : "r"(a[mi][0]), "r"(a[mi][1]), "r"(a[mi][2]), "r"(a[mi][3]),
                          "r"(b[ni][0]), "r"(b[ni][1]));
        }
        __syncthreads();
    }

    // epilogue
    float* Cbase = MODE ? g_ybuf : g_hbuf;
    const int ldc = MODE ? HIDDEN : O2;
    const int qrow = lane >> 2, qcol = (lane & 3) * 2;
    #pragma unroll
    for (int mi = 0; mi < 4; mi++) {
        int r0 = mBase + mi*16 + qrow;
        int a0 = s_arow[r0], a1 = s_arow[r0 + 8];
        float* C0 = (a0 >= 0) ? Cbase + (size_t)a0*ldc + n0 : nullptr;
        float* C1 = (a1 >= 0) ? Cbase + (size_t)a1*ldc + n0 : nullptr;
        #pragma unroll
        for (int ni = 0; ni < 4; ni++) {
            int c = nBase + ni*8 + qcol;
            if (C0) { C0[c] = acc[mi][ni][0]; C0[c+1] = acc[mi][ni][1]; }
            if (C1) { C1[c] = acc[mi][ni][2]; C1[c+1] = acc[mi][ni][3]; }
        }
    }
}

// ---------------- activation -> fp16 ----------------
__global__ void k_silu() {
    int i = blockIdx.x*blockDim.x + threadIdx.x;
    if (i < NASSIGN*INTER) {
        int a = i / INTER;
        int c = i - a*INTER;
        float g = g_hbuf[(size_t)a*O2 + c];
        float u = g_hbuf[(size_t)a*O2 + INTER + c];
        float v = (g / (1.0f + expf(-g))) * u;
        g_i[i] = __float2half_rn(v);
    }
}

// ---------------- combine ----------------
__global__ void k_comb(const float* __restrict__ wts, float* __restrict__ out) {
    int i = blockIdx.x*blockDim.x + threadIdx.x;
    if (i < TOKENS*HIDDEN) {
        int t = i >> 11;
        int h = i & (HIDDEN-1);
        float r = wts[2*t]   * g_ybuf[(size_t)(2*t)  *HIDDEN + h]
                + wts[2*t+1] * g_ybuf[(size_t)(2*t+1)*HIDDEN + h];
        out[i] = r;
    }
}

// ---------------- launch ----------------
extern "C" void kernel_launch(void* const* d_in, const int* in_sizes, int n_in,
                              void* d_out, int out_size) {
    const float* hidden  = (const float*)d_in[0];
    const int*   topk    = (const int*)  d_in[1];
    const float* topw    = (const float*)d_in[2];
    const float* gup_w   = (const float*)d_in[3];
    const float* dwn_w   = (const float*)d_in[4];
    const int*   gup_p   = (const int*)  d_in[5];
    const float* gup_a   = (const float*)d_in[6];
    const int*   dwn_p   = (const int*)  d_in[7];
    const float* dwn_a   = (const float*)d_in[8];
    const float* gup_ch  = (const float*)d_in[9];
    const float* dwn_ch  = (const float*)d_in[10];
    float* out = (float*)d_out;

    k_trig<<<(NROT*HIDDEN/2 + 255)/256, 256>>>(gup_a, dwn_a);
    k_prep<HIDDEN, true ><<<NE*O2,     256>>>(gup_w, gup_p, gup_ch);
    k_prep<INTER,  false><<<NE*HIDDEN, 256>>>(dwn_w, dwn_p, dwn_ch);
    k_hsplit<<<(TOKENS*HIDDEN + 255)/256, 256>>>(hidden);
    k_zero<<<1, 32>>>();
    k_route<<<(NASSIGN + 255)/256, 256>>>(topk);
    k_tiles<<<1, 32>>>();
    k_gemm<HIDDEN, 0><<<dim3(96, O2/128),     256>>>();
    k_silu<<<(NASSIGN*INTER + 255)/256, 256>>>();
    k_gemm<INTER,  1><<<dim3(96, HIDDEN/128), 256>>>();
    k_comb<<<(TOKENS*HIDDEN + 255)/256, 256>>>(topw, out);
}